// round 11
// baseline (speedup 1.0000x reference)
#include <cuda_runtime.h>
#include <cuda_bf16.h>
#include <mma.h>
#include <math.h>
#include <stdint.h>

using namespace nvcuda;

#define B 64
#define L 512
#define H 1024
#define NREL 3
#define KSPLIT 8
#define LSPLIT 8
#define MAT (NREL * B * H)      // 196608 floats per [3][64][1024] matrix

// Scratch (device globals — no allocation allowed)
__device__ float g_part[KSPLIT * MAT];    // split-K GEMM partials (reused 3x)
__device__ float g_hrel[MAT];             // tanh(concat @ W_rel)
__device__ float g_target[MAT];           // h_rel @ Win
__device__ float g_wpart[LSPLIT * MAT];   // weighted-ctx l-split partials (unnormalized)
__device__ float g_mstat[LSPLIT * NREL * B];  // per-split running max
__device__ float g_sstat[LSPLIT * NREL * B];  // per-split running sum
__device__ float g_wctx[MAT];             // weighted context
__device__ unsigned int g_ctr[NREL * 16]; // split-K completion counters (self-resetting)

// fp32 -> bf16 hi/lo split
__device__ __forceinline__ void bsplit(float f, __nv_bfloat16& hi, __nv_bfloat16& lo) {
    hi = __float2bfloat16(f);
    lo = __float2bfloat16(f - __bfloat162float(hi));
}

// ---------------------------------------------------------------------------
// Tensor-core (mma.sync/WMMA) split-K GEMM over A = concat(A1[64,1024],
// A2[64,1024]) (row-major, stride 1024), W row-major [(K1+K2), 1024].
// bf16 2-term split: D = Ah*Wh + Ah*Wl + Al*Wh, fp32 accumulate.
// Fused deterministic split-K reduction: each block stores its partial to
// Cpart[split][rel][64][1024]; the LAST block per (rel, n-tile) cell re-reads
// all KSPLIT partials in fixed order (__ldcg), sums, optional tanh, and writes
// either the reduced matrix (F==0) or the F-way broadcast output (F>0).
// BM=64, BN=64, BK=16; 8 warps in 4(m) x 2(n) grid, each warp 16x32.
// grid = (16 n-tiles, KSPLIT, 3 rels), block = 256.
// ---------------------------------------------------------------------------
__global__ __launch_bounds__(256) void gemm_wmma_kernel(
    const float* __restrict__ A1_0, const float* __restrict__ A1_1, const float* __restrict__ A1_2,
    const float* __restrict__ A2_0, const float* __restrict__ A2_1, const float* __restrict__ A2_2,
    const float* __restrict__ W0,  const float* __restrict__ W1,  const float* __restrict__ W2,
    float* __restrict__ Cpart, float* __restrict__ Cfinal,
    int K1len, int kchunk, int do_tanh, int F, unsigned int* __restrict__ ctr)
{
    const int rel = blockIdx.z;
    const float* A1 = (rel == 0) ? A1_0 : (rel == 1) ? A1_1 : A1_2;
    const float* A2 = (rel == 0) ? A2_0 : (rel == 1) ? A2_1 : A2_2;
    const float* W  = (rel == 0) ? W0  : (rel == 1) ? W1  : W2;
    float* C = Cpart + (size_t)blockIdx.y * MAT + (size_t)rel * (B * H);

    const int n0     = blockIdx.x * 64;
    const int kbeg   = blockIdx.y * kchunk;
    const int ntiles = kchunk / 16;

    // Padded ld (multiple of 8 bf16 = 16B, conflict-stagger)
    __shared__ __align__(16) __nv_bfloat16 Ah[64][24], Al[64][24];   // 6 KB
    __shared__ __align__(16) __nv_bfloat16 Wh[16][72], Wl[16][72];   // 4.5 KB

    const int tid  = threadIdx.x;
    const int warp = tid >> 5;
    const int wm   = warp >> 1;          // 0..3 : m-tile (16 rows)
    const int wn   = warp & 1;           // 0..1 : n-tile (32 cols)

    const int a_m = tid >> 2;            // 0..63
    const int a_k = (tid & 3) * 4;       // 0,4,8,12
    const int w_k = tid >> 4;            // 0..15
    const int w_n = (tid & 15) * 4;      // 0..60

    wmma::fragment<wmma::accumulator, 16, 16, 16, float> acc[2];
    wmma::fill_fragment(acc[0], 0.0f);
    wmma::fill_fragment(acc[1], 0.0f);

    // Prologue: load k-tile 0 (BK=16 tiles never straddle the concat boundary)
    int k0 = kbeg;
    const float* Aptr = (k0 < K1len)
        ? (A1 + (size_t)a_m * H + (k0 + a_k))
        : (A2 + (size_t)a_m * H + (k0 - K1len + a_k));
    float4 av = *(const float4*)Aptr;
    float4 wv = *(const float4*)(W + (size_t)(k0 + w_k) * H + n0 + w_n);

    for (int t = 0; t < ntiles; t++) {
        __syncthreads();                 // previous compute done — safe to overwrite
        {
            __nv_bfloat16 h, l;
            bsplit(av.x, h, l); Ah[a_m][a_k + 0] = h; Al[a_m][a_k + 0] = l;
            bsplit(av.y, h, l); Ah[a_m][a_k + 1] = h; Al[a_m][a_k + 1] = l;
            bsplit(av.z, h, l); Ah[a_m][a_k + 2] = h; Al[a_m][a_k + 2] = l;
            bsplit(av.w, h, l); Ah[a_m][a_k + 3] = h; Al[a_m][a_k + 3] = l;
            bsplit(wv.x, h, l); Wh[w_k][w_n + 0] = h; Wl[w_k][w_n + 0] = l;
            bsplit(wv.y, h, l); Wh[w_k][w_n + 1] = h; Wl[w_k][w_n + 1] = l;
            bsplit(wv.z, h, l); Wh[w_k][w_n + 2] = h; Wl[w_k][w_n + 2] = l;
            bsplit(wv.w, h, l); Wh[w_k][w_n + 3] = h; Wl[w_k][w_n + 3] = l;
        }
        __syncthreads();

        if (t + 1 < ntiles) {            // register prefetch of next k-tile
            int kn = kbeg + (t + 1) * 16;
            const float* Ap = (kn < K1len)
                ? (A1 + (size_t)a_m * H + (kn + a_k))
                : (A2 + (size_t)a_m * H + (kn - K1len + a_k));
            av = *(const float4*)Ap;
            wv = *(const float4*)(W + (size_t)(kn + w_k) * H + n0 + w_n);
        }

        wmma::fragment<wmma::matrix_a, 16, 16, 16, __nv_bfloat16, wmma::row_major> aH, aL;
        wmma::load_matrix_sync(aH, &Ah[wm * 16][0], 24);
        wmma::load_matrix_sync(aL, &Al[wm * 16][0], 24);
        #pragma unroll
        for (int j = 0; j < 2; j++) {
            wmma::fragment<wmma::matrix_b, 16, 16, 16, __nv_bfloat16, wmma::row_major> bH, bL;
            wmma::load_matrix_sync(bH, &Wh[0][wn * 32 + j * 16], 72);
            wmma::load_matrix_sync(bL, &Wl[0][wn * 32 + j * 16], 72);
            wmma::mma_sync(acc[j], aH, bH, acc[j]);
            wmma::mma_sync(acc[j], aH, bL, acc[j]);
            wmma::mma_sync(acc[j], aL, bH, acc[j]);
        }
    }

    #pragma unroll
    for (int j = 0; j < 2; j++)
        wmma::store_matrix_sync(C + (size_t)(wm * 16) * H + n0 + wn * 32 + j * 16,
                                acc[j], H, wmma::mem_row_major);

    // ---- Fused deterministic split-K reduction (threadFenceReduction) ----
    __shared__ int s_last;
    __syncthreads();                     // all partial stores issued
    if (tid == 0) {
        __threadfence();                 // release: partials visible device-wide
        unsigned int old = atomicAdd(&ctr[rel * gridDim.x + blockIdx.x], 1u);
        s_last = (old == KSPLIT - 1);
    }
    __syncthreads();
    if (s_last) {
        __threadfence();                 // acquire
        const int row = tid >> 2;
        const int cg  = (tid & 3) * 4;   // float4 group within the 16 per row
        const float4* p = (const float4*)Cpart;
        const size_t base = ((size_t)rel * (B * H) + (size_t)row * H + n0) / 4 + cg;
        #pragma unroll
        for (int q = 0; q < 4; q++) {
            float4 v = {0.f, 0.f, 0.f, 0.f};
            #pragma unroll
            for (int j = 0; j < KSPLIT; j++) {
                float4 a = __ldcg(&p[(size_t)j * (MAT / 4) + base + q]);
                v.x += a.x; v.y += a.y; v.z += a.z; v.w += a.w;
            }
            if (do_tanh) { v.x = tanhf(v.x); v.y = tanhf(v.y); v.z = tanhf(v.z); v.w = tanhf(v.w); }
            if (F == 0) {
                ((float4*)Cfinal)[base + q] = v;
            } else {                     // broadcast: out[rel][b][f][h]
                float4* o = (float4*)Cfinal
                          + ((size_t)(rel * B + row) * F) * 256 + (n0 / 4) + cg + q;
                for (int f = 0; f < F; f++) o[(size_t)f * 256] = v;
            }
        }
        __syncthreads();
        if (tid == 0) ctr[rel * gridDim.x + blockIdx.x] = 0;   // reset for replay
    }
}

// ---------------------------------------------------------------------------
// Flash-style single-pass attention with split-L online softmax.
// grid = (LSPLIT, 64 b), block = 256. enc read from DRAM exactly once.
// ---------------------------------------------------------------------------
__global__ __launch_bounds__(256) void attn_kernel(
    const float* __restrict__ enc, const float* __restrict__ target,
    float* __restrict__ wpart, float* __restrict__ mstat, float* __restrict__ sstat)
{
    const int ls   = blockIdx.x;
    const int b    = blockIdx.y;
    const int tid  = threadIdx.x;
    const int warp = tid >> 5;
    const int lane = tid & 31;

    __shared__ __align__(16) float st[3][H];      // 12 KB targets
    __shared__ __align__(16) float4 buf[8][256];  // 32 KB row chunk
    __shared__ float sch[3][8];                   // chunk scores
    __shared__ float s_p[3][8];                   // chunk unnormalized probs
    __shared__ float s_f[3];                      // rescale factor this chunk
    __shared__ float s_m[3], s_s[3];              // running max / sum

    for (int i = tid; i < 3 * H; i += 256)
        st[i >> 10][i & 1023] = target[(size_t)((i >> 10) * B + b) * H + (i & 1023)];
    if (tid < 3) { s_m[tid] = -1e30f; s_s[tid] = 0.f; }
    __syncthreads();

    float4 a0 = {0,0,0,0}, a1 = {0,0,0,0}, a2 = {0,0,0,0};

    for (int c = 0; c < 8; c++) {
        // Load 8 rows (warp w -> row w) into smem, computing score dots on the fly
        {
            const int l = ls * 64 + c * 8 + warp;
            const float4* erow = (const float4*)(enc + ((size_t)b * L + l) * H);
            float d0 = 0.f, d1 = 0.f, d2 = 0.f;
            #pragma unroll
            for (int i = 0; i < 8; i++) {
                int h4 = lane + i * 32;
                float4 e = erow[h4];
                buf[warp][h4] = e;
                float4 t0 = *(const float4*)&st[0][h4 * 4];
                float4 t1 = *(const float4*)&st[1][h4 * 4];
                float4 t2 = *(const float4*)&st[2][h4 * 4];
                d0 += e.x * t0.x + e.y * t0.y + e.z * t0.z + e.w * t0.w;
                d1 += e.x * t1.x + e.y * t1.y + e.z * t1.z + e.w * t1.w;
                d2 += e.x * t2.x + e.y * t2.y + e.z * t2.z + e.w * t2.w;
            }
            #pragma unroll
            for (int o = 16; o > 0; o >>= 1) {
                d0 += __shfl_down_sync(0xffffffffu, d0, o);
                d1 += __shfl_down_sync(0xffffffffu, d1, o);
                d2 += __shfl_down_sync(0xffffffffu, d2, o);
            }
            if (lane == 0) { sch[0][warp] = d0; sch[1][warp] = d1; sch[2][warp] = d2; }
        }
        __syncthreads();

        // Online softmax update (threads 0..2, one per rel)
        if (tid < 3) {
            const int r = tid;
            float m_new = s_m[r];
            #pragma unroll
            for (int j = 0; j < 8; j++) m_new = fmaxf(m_new, sch[r][j]);
            float f = __expf(s_m[r] - m_new);     // exp(-inf - m) = 0 on first chunk
            float s = s_s[r] * f;
            #pragma unroll
            for (int j = 0; j < 8; j++) {
                float p = __expf(sch[r][j] - m_new);
                s_p[r][j] = p;
                s += p;
            }
            s_m[r] = m_new; s_s[r] = s; s_f[r] = f;
        }
        __syncthreads();

        // Rescale accumulators, then add this chunk's weighted rows
        {
            float f0 = s_f[0], f1 = s_f[1], f2 = s_f[2];
            a0.x *= f0; a0.y *= f0; a0.z *= f0; a0.w *= f0;
            a1.x *= f1; a1.y *= f1; a1.z *= f1; a1.w *= f1;
            a2.x *= f2; a2.y *= f2; a2.z *= f2; a2.w *= f2;
            #pragma unroll
            for (int l = 0; l < 8; l++) {
                float4 e = buf[l][tid];
                float p0 = s_p[0][l], p1 = s_p[1][l], p2 = s_p[2][l];
                a0.x += p0 * e.x; a0.y += p0 * e.y; a0.z += p0 * e.z; a0.w += p0 * e.w;
                a1.x += p1 * e.x; a1.y += p1 * e.y; a1.z += p1 * e.z; a1.w += p1 * e.w;
                a2.x += p2 * e.x; a2.y += p2 * e.y; a2.z += p2 * e.z; a2.w += p2 * e.w;
            }
        }
        __syncthreads();   // buf/sch reused next chunk
    }

    float4* w = (float4*)(wpart + (size_t)ls * MAT);
    w[(size_t)(0 * B + b) * 256 + tid] = a0;
    w[(size_t)(1 * B + b) * 256 + tid] = a1;
    w[(size_t)(2 * B + b) * 256 + tid] = a2;
    if (tid < 3) {
        mstat[ls * (NREL * B) + tid * B + b] = s_m[tid];
        sstat[ls * (NREL * B) + tid * B + b] = s_s[tid];
    }
}

// Merge l-split partials: exact softmax via per-split (m, s) stats.
// One block per (rel, b) = 192 blocks, 256 threads (one float4 h-col each).
__global__ __launch_bounds__(256) void combine_kernel(
    const float* __restrict__ wpart, const float* __restrict__ mstat,
    const float* __restrict__ sstat, float* __restrict__ wctx)
{
    const int rb  = blockIdx.x;          // rel*64 + b
    const int tid = threadIdx.x;
    __shared__ float wsc[LSPLIT];

    if (tid == 0) {
        float m[LSPLIT], M = -1e30f;
        #pragma unroll
        for (int j = 0; j < LSPLIT; j++) { m[j] = mstat[j * (NREL * B) + rb]; M = fmaxf(M, m[j]); }
        float T = 0.f, e[LSPLIT];
        #pragma unroll
        for (int j = 0; j < LSPLIT; j++) {
            e[j] = __expf(m[j] - M);
            T += sstat[j * (NREL * B) + rb] * e[j];
        }
        float inv = 1.f / T;
        #pragma unroll
        for (int j = 0; j < LSPLIT; j++) wsc[j] = e[j] * inv;
    }
    __syncthreads();

    const float4* p = (const float4*)wpart;
    float4 v = {0,0,0,0};
    #pragma unroll
    for (int j = 0; j < LSPLIT; j++) {
        float4 a = p[(size_t)j * (MAT / 4) + (size_t)rb * 256 + tid];
        float s = wsc[j];
        v.x += s * a.x; v.y += s * a.y; v.z += s * a.z; v.w += s * a.w;
    }
    ((float4*)wctx)[(size_t)rb * 256 + tid] = v;
}

// ---------------------------------------------------------------------------
extern "C" void kernel_launch(void* const* d_in, const int* in_sizes, int n_in,
                              void* d_out, int out_size)
{
    const float* h_s     = (const float*)d_in[0];
    const float* h_o     = (const float*)d_in[1];
    const float* h_a     = (const float*)d_in[2];
    const float* enc     = (const float*)d_in[3];
    // d_in[4] = full_feature_len (derived from out_size instead)
    const float* W_as    = (const float*)d_in[5];
    const float* W_so    = (const float*)d_in[6];
    const float* W_oa    = (const float*)d_in[7];
    const float* Win_as  = (const float*)d_in[8];
    const float* Win_so  = (const float*)d_in[9];
    const float* Win_oa  = (const float*)d_in[10];
    const float* Wout_as = (const float*)d_in[11];
    const float* Wout_so = (const float*)d_in[12];
    const float* Wout_oa = (const float*)d_in[13];
    float* out = (float*)d_out;
    const int F = out_size / (NREL * B * H);       // 36

    float *p_part, *p_hrel, *p_target, *p_wpart, *p_mstat, *p_sstat, *p_wctx;
    unsigned int* p_ctr;
    cudaGetSymbolAddress((void**)&p_part,   g_part);
    cudaGetSymbolAddress((void**)&p_hrel,   g_hrel);
    cudaGetSymbolAddress((void**)&p_target, g_target);
    cudaGetSymbolAddress((void**)&p_wpart,  g_wpart);
    cudaGetSymbolAddress((void**)&p_mstat,  g_mstat);
    cudaGetSymbolAddress((void**)&p_sstat,  g_sstat);
    cudaGetSymbolAddress((void**)&p_wctx,   g_wctx);
    cudaGetSymbolAddress((void**)&p_ctr,    g_ctr);

    const dim3 gg(16, KSPLIT, 3);                  // 384 blocks

    // 1) h_rel = tanh(concat(h1,h2) @ W_rel)  — fused reduce+tanh
    gemm_wmma_kernel<<<gg, 256>>>(h_a, h_s, h_o,   h_s, h_o, h_a,
                                  W_as, W_so, W_oa, p_part, p_hrel,
                                  H, 2 * H / KSPLIT, 1, 0, p_ctr);

    // 2) target = h_rel @ Win_rel  — fused reduce
    gemm_wmma_kernel<<<gg, 256>>>(p_hrel, p_hrel + B * H, p_hrel + 2 * B * H,
                                  p_hrel, p_hrel, p_hrel,   // unused (K1len = 2H)
                                  Win_as, Win_so, Win_oa, p_part, p_target,
                                  2 * H, H / KSPLIT, 0, 0, p_ctr);

    // 3) single-pass flash attention (scores+softmax+wctx), then split combine
    attn_kernel<<<dim3(LSPLIT, 64), 256>>>(enc, p_target, p_wpart, p_mstat, p_sstat);
    combine_kernel<<<192, 256>>>(p_wpart, p_mstat, p_sstat, p_wctx);

    // 4) h_final = tanh(concat(wctx, h_rel) @ Wout_rel) — fused reduce+tanh+broadcast
    gemm_wmma_kernel<<<gg, 256>>>(p_wctx, p_wctx + B * H, p_wctx + 2 * B * H,
                                  p_hrel, p_hrel + B * H, p_hrel + 2 * B * H,
                                  Wout_as, Wout_so, Wout_oa, p_part, out,
                                  H, 2 * H / KSPLIT, 1, F, p_ctr);
}

// round 14
// speedup vs baseline: 1.6604x; 1.6604x over previous
#include <cuda_runtime.h>
#include <cuda_bf16.h>
#include <mma.h>
#include <math.h>
#include <stdint.h>

using namespace nvcuda;

#define B 64
#define L 512
#define H 1024
#define NREL 3
#define KSPLIT 8
#define LSPLIT 8
#define MAT (NREL * B * H)      // 196608 floats per [3][64][1024] matrix

// Scratch (device globals — no allocation allowed)
__device__ float g_part[KSPLIT * MAT];    // split-K GEMM partials (reused 3x)
__device__ float g_hrel[MAT];             // tanh(concat @ W_rel)
__device__ float g_target[MAT];           // h_rel @ Win
__device__ float g_wpart[LSPLIT * MAT];   // weighted-ctx l-split partials (unnormalized)
__device__ float g_mstat[LSPLIT * NREL * B];  // per-split running max
__device__ float g_sstat[LSPLIT * NREL * B];  // per-split running sum
__device__ float g_wctx[MAT];             // weighted context

// fp32x4 -> packed bf16 hi/lo (two uint2: 4 hi bf16, 4 lo bf16)
__device__ __forceinline__ void bsplit4(float4 v, uint2& hv, uint2& lv) {
    __nv_bfloat162 ha = __floats2bfloat162_rn(v.x, v.y);
    __nv_bfloat162 hb = __floats2bfloat162_rn(v.z, v.w);
    __nv_bfloat162 la = __floats2bfloat162_rn(v.x - __bfloat162float(ha.x),
                                              v.y - __bfloat162float(ha.y));
    __nv_bfloat162 lb = __floats2bfloat162_rn(v.z - __bfloat162float(hb.x),
                                              v.w - __bfloat162float(hb.y));
    hv.x = *(uint32_t*)&ha; hv.y = *(uint32_t*)&hb;
    lv.x = *(uint32_t*)&la; lv.y = *(uint32_t*)&lb;
}

// ---------------------------------------------------------------------------
// Tensor-core (mma.sync/WMMA) split-K GEMM over A = concat(A1[64,1024],
// A2[64,1024]) (row-major, stride 1024), W row-major [(K1+K2), 1024].
// bf16 2-term split: D = Ah*Wh + Ah*Wl + Al*Wh, fp32 accumulate.
// Plain (non-atomic) partials: Cpart[split][rel][64][1024].
// BM=64, BN=64, BK=16; 8 warps in 4(m) x 2(n) grid, each warp 16x32.
// R9 structure (single buffer, 2 syncs/tile, register prefetch) with packed
// STS.64 conversion stores (R12).
// grid = (16 n-tiles, KSPLIT, 3 rels), block = 256.
// ---------------------------------------------------------------------------
__global__ __launch_bounds__(256) void gemm_wmma_kernel(
    const float* __restrict__ A1_0, const float* __restrict__ A1_1, const float* __restrict__ A1_2,
    const float* __restrict__ A2_0, const float* __restrict__ A2_1, const float* __restrict__ A2_2,
    const float* __restrict__ W0,  const float* __restrict__ W1,  const float* __restrict__ W2,
    float* __restrict__ Cpart, int K1len, int kchunk)
{
    const int rel = blockIdx.z;
    const float* A1 = (rel == 0) ? A1_0 : (rel == 1) ? A1_1 : A1_2;
    const float* A2 = (rel == 0) ? A2_0 : (rel == 1) ? A2_1 : A2_2;
    const float* W  = (rel == 0) ? W0  : (rel == 1) ? W1  : W2;
    float* C = Cpart + (size_t)blockIdx.y * MAT + (size_t)rel * (B * H);

    const int n0     = blockIdx.x * 64;
    const int kbeg   = blockIdx.y * kchunk;
    const int ntiles = kchunk / 16;

    // Padded ld (multiple of 8 bf16 = 16B, conflict-stagger; STS.64-aligned slots)
    __shared__ __align__(16) __nv_bfloat16 Ah[64][24], Al[64][24];   // 6 KB
    __shared__ __align__(16) __nv_bfloat16 Wh[16][72], Wl[16][72];   // 4.5 KB

    const int tid  = threadIdx.x;
    const int warp = tid >> 5;
    const int wm   = warp >> 1;          // 0..3 : m-tile (16 rows)
    const int wn   = warp & 1;           // 0..1 : n-tile (32 cols)

    const int a_m = tid >> 2;            // 0..63
    const int a_k = (tid & 3) * 4;       // 0,4,8,12
    const int w_k = tid >> 4;            // 0..15
    const int w_n = (tid & 15) * 4;      // 0..60

    wmma::fragment<wmma::accumulator, 16, 16, 16, float> acc[2];
    wmma::fill_fragment(acc[0], 0.0f);
    wmma::fill_fragment(acc[1], 0.0f);

    // Prologue: load k-tile 0 (BK=16 tiles never straddle the concat boundary)
    int k0 = kbeg;
    const float* Aptr = (k0 < K1len)
        ? (A1 + (size_t)a_m * H + (k0 + a_k))
        : (A2 + (size_t)a_m * H + (k0 - K1len + a_k));
    float4 av = *(const float4*)Aptr;
    float4 wv = *(const float4*)(W + (size_t)(k0 + w_k) * H + n0 + w_n);

    for (int t = 0; t < ntiles; t++) {
        __syncthreads();                 // previous compute done — safe to overwrite
        {
            uint2 hv, lv;
            bsplit4(av, hv, lv);
            *(uint2*)&Ah[a_m][a_k] = hv;
            *(uint2*)&Al[a_m][a_k] = lv;
            bsplit4(wv, hv, lv);
            *(uint2*)&Wh[w_k][w_n] = hv;
            *(uint2*)&Wl[w_k][w_n] = lv;
        }
        __syncthreads();

        if (t + 1 < ntiles) {            // register prefetch of next k-tile
            int kn = kbeg + (t + 1) * 16;
            const float* Ap = (kn < K1len)
                ? (A1 + (size_t)a_m * H + (kn + a_k))
                : (A2 + (size_t)a_m * H + (kn - K1len + a_k));
            av = *(const float4*)Ap;
            wv = *(const float4*)(W + (size_t)(kn + w_k) * H + n0 + w_n);
        }

        wmma::fragment<wmma::matrix_a, 16, 16, 16, __nv_bfloat16, wmma::row_major> aH, aL;
        wmma::load_matrix_sync(aH, &Ah[wm * 16][0], 24);
        wmma::load_matrix_sync(aL, &Al[wm * 16][0], 24);
        #pragma unroll
        for (int j = 0; j < 2; j++) {
            wmma::fragment<wmma::matrix_b, 16, 16, 16, __nv_bfloat16, wmma::row_major> bH, bL;
            wmma::load_matrix_sync(bH, &Wh[0][wn * 32 + j * 16], 72);
            wmma::load_matrix_sync(bL, &Wl[0][wn * 32 + j * 16], 72);
            wmma::mma_sync(acc[j], aH, bH, acc[j]);
            wmma::mma_sync(acc[j], aH, bL, acc[j]);
            wmma::mma_sync(acc[j], aL, bH, acc[j]);
        }
    }

    #pragma unroll
    for (int j = 0; j < 2; j++)
        wmma::store_matrix_sync(C + (size_t)(wm * 16) * H + n0 + wn * 32 + j * 16,
                                acc[j], H, wmma::mem_row_major);
}

// Deterministic 8-way split reduction (+ optional tanh), float4-vectorized.
__global__ void reduce8_kernel(const float* __restrict__ in, float* __restrict__ outp, int do_tanh)
{
    int i = blockIdx.x * 256 + threadIdx.x;        // float4 index, 0..49151
    const int S = MAT / 4;
    if (i >= S) return;
    const float4* p = (const float4*)in;
    float4 v = p[i];
    #pragma unroll
    for (int j = 1; j < KSPLIT; j++) {
        float4 a = p[i + j * S];
        v.x += a.x; v.y += a.y; v.z += a.z; v.w += a.w;
    }
    if (do_tanh) { v.x = tanhf(v.x); v.y = tanhf(v.y); v.z = tanhf(v.z); v.w = tanhf(v.w); }
    ((float4*)outp)[i] = v;
}

// ---------------------------------------------------------------------------
// Flash-style single-pass attention with split-L online softmax.
// grid = (LSPLIT, 64 b), block = 256. enc read from DRAM exactly once.
// ---------------------------------------------------------------------------
__global__ __launch_bounds__(256) void attn_kernel(
    const float* __restrict__ enc, const float* __restrict__ target,
    float* __restrict__ wpart, float* __restrict__ mstat, float* __restrict__ sstat)
{
    const int ls   = blockIdx.x;
    const int b    = blockIdx.y;
    const int tid  = threadIdx.x;
    const int warp = tid >> 5;
    const int lane = tid & 31;

    __shared__ __align__(16) float st[3][H];      // 12 KB targets
    __shared__ __align__(16) float4 buf[8][256];  // 32 KB row chunk
    __shared__ float sch[3][8];                   // chunk scores
    __shared__ float s_p[3][8];                   // chunk unnormalized probs
    __shared__ float s_f[3];                      // rescale factor this chunk
    __shared__ float s_m[3], s_s[3];              // running max / sum

    for (int i = tid; i < 3 * H; i += 256)
        st[i >> 10][i & 1023] = target[(size_t)((i >> 10) * B + b) * H + (i & 1023)];
    if (tid < 3) { s_m[tid] = -1e30f; s_s[tid] = 0.f; }
    __syncthreads();

    float4 a0 = {0,0,0,0}, a1 = {0,0,0,0}, a2 = {0,0,0,0};

    for (int c = 0; c < 8; c++) {
        // Load 8 rows (warp w -> row w) into smem, computing score dots on the fly
        {
            const int l = ls * 64 + c * 8 + warp;
            const float4* erow = (const float4*)(enc + ((size_t)b * L + l) * H);
            float d0 = 0.f, d1 = 0.f, d2 = 0.f;
            #pragma unroll
            for (int i = 0; i < 8; i++) {
                int h4 = lane + i * 32;
                float4 e = erow[h4];
                buf[warp][h4] = e;
                float4 t0 = *(const float4*)&st[0][h4 * 4];
                float4 t1 = *(const float4*)&st[1][h4 * 4];
                float4 t2 = *(const float4*)&st[2][h4 * 4];
                d0 += e.x * t0.x + e.y * t0.y + e.z * t0.z + e.w * t0.w;
                d1 += e.x * t1.x + e.y * t1.y + e.z * t1.z + e.w * t1.w;
                d2 += e.x * t2.x + e.y * t2.y + e.z * t2.z + e.w * t2.w;
            }
            #pragma unroll
            for (int o = 16; o > 0; o >>= 1) {
                d0 += __shfl_down_sync(0xffffffffu, d0, o);
                d1 += __shfl_down_sync(0xffffffffu, d1, o);
                d2 += __shfl_down_sync(0xffffffffu, d2, o);
            }
            if (lane == 0) { sch[0][warp] = d0; sch[1][warp] = d1; sch[2][warp] = d2; }
        }
        __syncthreads();

        // Online softmax update (threads 0..2, one per rel)
        if (tid < 3) {
            const int r = tid;
            float m_new = s_m[r];
            #pragma unroll
            for (int j = 0; j < 8; j++) m_new = fmaxf(m_new, sch[r][j]);
            float f = __expf(s_m[r] - m_new);     // exp(-inf - m) = 0 on first chunk
            float s = s_s[r] * f;
            #pragma unroll
            for (int j = 0; j < 8; j++) {
                float p = __expf(sch[r][j] - m_new);
                s_p[r][j] = p;
                s += p;
            }
            s_m[r] = m_new; s_s[r] = s; s_f[r] = f;
        }
        __syncthreads();

        // Rescale accumulators, then add this chunk's weighted rows
        {
            float f0 = s_f[0], f1 = s_f[1], f2 = s_f[2];
            a0.x *= f0; a0.y *= f0; a0.z *= f0; a0.w *= f0;
            a1.x *= f1; a1.y *= f1; a1.z *= f1; a1.w *= f1;
            a2.x *= f2; a2.y *= f2; a2.z *= f2; a2.w *= f2;
            #pragma unroll
            for (int l = 0; l < 8; l++) {
                float4 e = buf[l][tid];
                float p0 = s_p[0][l], p1 = s_p[1][l], p2 = s_p[2][l];
                a0.x += p0 * e.x; a0.y += p0 * e.y; a0.z += p0 * e.z; a0.w += p0 * e.w;
                a1.x += p1 * e.x; a1.y += p1 * e.y; a1.z += p1 * e.z; a1.w += p1 * e.w;
                a2.x += p2 * e.x; a2.y += p2 * e.y; a2.z += p2 * e.z; a2.w += p2 * e.w;
            }
        }
        __syncthreads();   // buf/sch reused next chunk
    }

    float4* w = (float4*)(wpart + (size_t)ls * MAT);
    w[(size_t)(0 * B + b) * 256 + tid] = a0;
    w[(size_t)(1 * B + b) * 256 + tid] = a1;
    w[(size_t)(2 * B + b) * 256 + tid] = a2;
    if (tid < 3) {
        mstat[ls * (NREL * B) + tid * B + b] = s_m[tid];
        sstat[ls * (NREL * B) + tid * B + b] = s_s[tid];
    }
}

// Merge l-split partials: exact softmax via per-split (m, s) stats.
// One block per (rel, b) = 192 blocks, 256 threads (one float4 h-col each).
__global__ __launch_bounds__(256) void combine_kernel(
    const float* __restrict__ wpart, const float* __restrict__ mstat,
    const float* __restrict__ sstat, float* __restrict__ wctx)
{
    const int rb  = blockIdx.x;          // rel*64 + b
    const int tid = threadIdx.x;
    __shared__ float wsc[LSPLIT];

    if (tid == 0) {
        float m[LSPLIT], M = -1e30f;
        #pragma unroll
        for (int j = 0; j < LSPLIT; j++) { m[j] = mstat[j * (NREL * B) + rb]; M = fmaxf(M, m[j]); }
        float T = 0.f, e[LSPLIT];
        #pragma unroll
        for (int j = 0; j < LSPLIT; j++) {
            e[j] = __expf(m[j] - M);
            T += sstat[j * (NREL * B) + rb] * e[j];
        }
        float inv = 1.f / T;
        #pragma unroll
        for (int j = 0; j < LSPLIT; j++) wsc[j] = e[j] * inv;
    }
    __syncthreads();

    const float4* p = (const float4*)wpart;
    float4 v = {0,0,0,0};
    #pragma unroll
    for (int j = 0; j < LSPLIT; j++) {
        float4 a = p[(size_t)j * (MAT / 4) + (size_t)rb * 256 + tid];
        float s = wsc[j];
        v.x += s * a.x; v.y += s * a.y; v.z += s * a.z; v.w += s * a.w;
    }
    ((float4*)wctx)[(size_t)rb * 256 + tid] = v;
}

// Sum final-GEMM split-K partials, tanh, broadcast F times to out[rel][b][f][h].
__global__ void bcast_kernel(const float* __restrict__ part, float* __restrict__ out, int F)
{
    int idx = blockIdx.x * 256 + threadIdx.x;      // 0..49151 float4 units
    const float4* p = (const float4*)part;
    const int S = MAT / 4;
    float4 v = p[idx];
    #pragma unroll
    for (int j = 1; j < KSPLIT; j++) {
        float4 a = p[idx + j * S];
        v.x += a.x; v.y += a.y; v.z += a.z; v.w += a.w;
    }
    v.x = tanhf(v.x); v.y = tanhf(v.y); v.z = tanhf(v.z); v.w = tanhf(v.w);
    int rb = idx >> 8;                             // rel*64 + b
    int h4 = idx & 255;
    float4* o = (float4*)out + (size_t)rb * F * 256 + h4;
    for (int f = 0; f < F; f++) o[(size_t)f * 256] = v;
}

// ---------------------------------------------------------------------------
extern "C" void kernel_launch(void* const* d_in, const int* in_sizes, int n_in,
                              void* d_out, int out_size)
{
    const float* h_s     = (const float*)d_in[0];
    const float* h_o     = (const float*)d_in[1];
    const float* h_a     = (const float*)d_in[2];
    const float* enc     = (const float*)d_in[3];
    // d_in[4] = full_feature_len (derived from out_size instead)
    const float* W_as    = (const float*)d_in[5];
    const float* W_so    = (const float*)d_in[6];
    const float* W_oa    = (const float*)d_in[7];
    const float* Win_as  = (const float*)d_in[8];
    const float* Win_so  = (const float*)d_in[9];
    const float* Win_oa  = (const float*)d_in[10];
    const float* Wout_as = (const float*)d_in[11];
    const float* Wout_so = (const float*)d_in[12];
    const float* Wout_oa = (const float*)d_in[13];
    float* out = (float*)d_out;
    const int F = out_size / (NREL * B * H);       // 36

    float *p_part, *p_hrel, *p_target, *p_wpart, *p_mstat, *p_sstat, *p_wctx;
    cudaGetSymbolAddress((void**)&p_part,   g_part);
    cudaGetSymbolAddress((void**)&p_hrel,   g_hrel);
    cudaGetSymbolAddress((void**)&p_target, g_target);
    cudaGetSymbolAddress((void**)&p_wpart,  g_wpart);
    cudaGetSymbolAddress((void**)&p_mstat,  g_mstat);
    cudaGetSymbolAddress((void**)&p_sstat,  g_sstat);
    cudaGetSymbolAddress((void**)&p_wctx,   g_wctx);

    const dim3 gg(16, KSPLIT, 3);                  // 384 blocks

    // 1) h_rel = tanh(concat(h1,h2) @ W_rel)   [as: (a,s), so: (s,o), oa: (o,a)]
    gemm_wmma_kernel<<<gg, 256>>>(h_a, h_s, h_o,   h_s, h_o, h_a,
                                  W_as, W_so, W_oa, p_part, H, 2 * H / KSPLIT);
    reduce8_kernel<<<192, 256>>>(p_part, p_hrel, 1);

    // 2) target = h_rel @ Win_rel
    gemm_wmma_kernel<<<gg, 256>>>(p_hrel, p_hrel + B * H, p_hrel + 2 * B * H,
                                  p_hrel, p_hrel, p_hrel,   // unused (K1len = 2H)
                                  Win_as, Win_so, Win_oa, p_part, 2 * H, H / KSPLIT);
    reduce8_kernel<<<192, 256>>>(p_part, p_target, 0);

    // 3) single-pass flash attention (scores+softmax+wctx), then split combine
    attn_kernel<<<dim3(LSPLIT, 64), 256>>>(enc, p_target, p_wpart, p_mstat, p_sstat);
    combine_kernel<<<192, 256>>>(p_wpart, p_mstat, p_sstat, p_wctx);

    // 4) h_final = tanh(concat(wctx, h_rel) @ Wout_rel), broadcast to out
    gemm_wmma_kernel<<<gg, 256>>>(p_wctx, p_wctx + B * H, p_wctx + 2 * B * H,
                                  p_hrel, p_hrel + B * H, p_hrel + 2 * B * H,
                                  Wout_as, Wout_so, Wout_oa, p_part, H, 2 * H / KSPLIT);
    bcast_kernel<<<192, 256>>>(p_part, out, F);
}